// round 6
// baseline (speedup 1.0000x reference)
#include <cuda_runtime.h>

#define N_NODES_MAX 100000
#define D_FEAT 32
#define SCAN_BLK 512

// Scratch (no cudaMalloc allowed)
__device__ int    g_deg_out[N_NODES_MAX];
__device__ int    g_deg_in [N_NODES_MAX];
__device__ float  g_norm   [N_NODES_MAX];
__device__ float4 g_x4     [N_NODES_MAX * (D_FEAT / 4)];
__device__ int    g_scan_tmp[N_NODES_MAX];
__device__ int    g_bsum[SCAN_BLK];
__device__ int    g_bpre[SCAN_BLK];
__device__ int    g_ofs[N_NODES_MAX];
__device__ int    g_cur[N_NODES_MAX];
__device__ int    g_csrc[1600000];     // CSR source ids (N_EDGES)

// ---------------------------------------------------------------------------
// 1: zero both degree arrays.
// ---------------------------------------------------------------------------
__global__ void k_init(int n_nodes)
{
    int i = blockIdx.x * blockDim.x + threadIdx.x;
    if (i < n_nodes) { g_deg_out[i] = 0; g_deg_in[i] = 0; }
}

// ---------------------------------------------------------------------------
// 2: out-degree of src (for norm) and in-degree of dst (for CSR).
// ---------------------------------------------------------------------------
__global__ void k_degrees(const int4* __restrict__ src4,
                          const int4* __restrict__ dst4,
                          const int*  __restrict__ src,
                          const int*  __restrict__ dst,
                          int n4, int n_edges)
{
    int i = blockIdx.x * blockDim.x + threadIdx.x;
    if (i < n4) {
        int4 s = __ldg(&src4[i]);
        int4 d = __ldg(&dst4[i]);
        atomicAdd(&g_deg_out[s.x], 1); atomicAdd(&g_deg_out[s.y], 1);
        atomicAdd(&g_deg_out[s.z], 1); atomicAdd(&g_deg_out[s.w], 1);
        atomicAdd(&g_deg_in [d.x], 1); atomicAdd(&g_deg_in [d.y], 1);
        atomicAdd(&g_deg_in [d.z], 1); atomicAdd(&g_deg_in [d.w], 1);
    }
    if (i == 0) {
        for (int e = n4 * 4; e < n_edges; e++) {
            atomicAdd(&g_deg_out[src[e]], 1);
            atomicAdd(&g_deg_in [dst[e]], 1);
        }
    }
}

// ---------------------------------------------------------------------------
// 3: norm = rsqrt(out-degree); prescale x = feat * norm[node].
// ---------------------------------------------------------------------------
__global__ void k_prescale(const float4* __restrict__ feat4, int n_nodes)
{
    int i = blockIdx.x * blockDim.x + threadIdx.x;
    int total4 = n_nodes * (D_FEAT / 4);
    if (i >= total4) return;
    int n = i >> 3;
    int deg = __ldg(&g_deg_out[n]);
    float norm = (deg > 0) ? rsqrtf((float)deg) : 0.0f;
    if ((i & 7) == 0) g_norm[n] = norm;
    float4 f = __ldg(&feat4[i]);
    g_x4[i] = make_float4(f.x * norm, f.y * norm, f.z * norm, f.w * norm);
}

// ---------------------------------------------------------------------------
// 4a: per-block inclusive scan of in-degrees + block sums.
// ---------------------------------------------------------------------------
__global__ void k_scanA(int n_nodes)
{
    __shared__ int sh[2][SCAN_BLK];
    int tid = threadIdx.x;
    int gid = blockIdx.x * SCAN_BLK + tid;
    int v = (gid < n_nodes) ? g_deg_in[gid] : 0;
    int buf = 0;
    sh[0][tid] = v;
    __syncthreads();
    #pragma unroll
    for (int off = 1; off < SCAN_BLK; off <<= 1) {
        int nv = sh[buf][tid] + ((tid >= off) ? sh[buf][tid - off] : 0);
        sh[buf ^ 1][tid] = nv;
        buf ^= 1;
        __syncthreads();
    }
    int incl = sh[buf][tid];
    if (gid < n_nodes) g_scan_tmp[gid] = incl;
    if (tid == SCAN_BLK - 1) g_bsum[blockIdx.x] = incl;
}

// ---------------------------------------------------------------------------
// 4b: scan block sums (single block; nblocks <= SCAN_BLK).
// ---------------------------------------------------------------------------
__global__ void k_scanB(int nblocks)
{
    __shared__ int sh[2][SCAN_BLK];
    int tid = threadIdx.x;
    int v = (tid < nblocks) ? g_bsum[tid] : 0;
    int buf = 0;
    sh[0][tid] = v;
    __syncthreads();
    #pragma unroll
    for (int off = 1; off < SCAN_BLK; off <<= 1) {
        int nv = sh[buf][tid] + ((tid >= off) ? sh[buf][tid - off] : 0);
        sh[buf ^ 1][tid] = nv;
        buf ^= 1;
        __syncthreads();
    }
    if (tid < nblocks) g_bpre[tid] = sh[buf][tid] - v;   // exclusive
}

// ---------------------------------------------------------------------------
// 4c: node offsets (exclusive) and cursors.
// ---------------------------------------------------------------------------
__global__ void k_scanC(int n_nodes)
{
    int gid = blockIdx.x * SCAN_BLK + threadIdx.x;
    if (gid >= n_nodes) return;
    int ofs = g_bpre[blockIdx.x] + g_scan_tmp[gid] - g_deg_in[gid];
    g_ofs[gid] = ofs;
    g_cur[gid] = ofs;
}

// ---------------------------------------------------------------------------
// 5: bucket edges by dst (counting sort): csrc[pos] = src.
// ---------------------------------------------------------------------------
__global__ void k_bucket(const int4* __restrict__ src4,
                         const int4* __restrict__ dst4,
                         const int*  __restrict__ src,
                         const int*  __restrict__ dst,
                         int n4, int n_edges)
{
    int i = blockIdx.x * blockDim.x + threadIdx.x;
    if (i < n4) {
        int4 s = __ldg(&src4[i]);
        int4 d = __ldg(&dst4[i]);
        int p0 = atomicAdd(&g_cur[d.x], 1); g_csrc[p0] = s.x;
        int p1 = atomicAdd(&g_cur[d.y], 1); g_csrc[p1] = s.y;
        int p2 = atomicAdd(&g_cur[d.z], 1); g_csrc[p2] = s.z;
        int p3 = atomicAdd(&g_cur[d.w], 1); g_csrc[p3] = s.w;
    }
    if (i == 0) {
        for (int e = n4 * 4; e < n_edges; e++) {
            int p = atomicAdd(&g_cur[dst[e]], 1);
            g_csrc[p] = src[e];
        }
    }
}

// ---------------------------------------------------------------------------
// 6: gather.  Warp = 4 nodes x 8 lanes; per in-edge one LDG.128 of prescaled
// x[src]; register accumulation (2 accumulators); one streaming write of
// out[t] = acc * norm[t].  No atomics, no out zero-init, no postscale pass.
// ---------------------------------------------------------------------------
__global__ void k_gather(float4* __restrict__ out4, int n_nodes)
{
    int gtid = blockIdx.x * blockDim.x + threadIdx.x;
    int warp = gtid >> 5;
    int lane = gtid & 31;
    int grp  = lane >> 3;
    int c    = lane & 7;
    int t    = warp * 4 + grp;
    if (t >= n_nodes) return;

    int start = __ldg(&g_ofs[t]);
    int len   = __ldg(&g_deg_in[t]);

    float4 a0 = make_float4(0.f, 0.f, 0.f, 0.f);
    float4 a1 = make_float4(0.f, 0.f, 0.f, 0.f);

    int j = 0;
    for (; j + 1 < len; j += 2) {
        int s0 = __ldg(&g_csrc[start + j]);
        int s1 = __ldg(&g_csrc[start + j + 1]);
        float4 f0 = __ldg(&g_x4[s0 * (D_FEAT / 4) + c]);
        float4 f1 = __ldg(&g_x4[s1 * (D_FEAT / 4) + c]);
        a0.x += f0.x; a0.y += f0.y; a0.z += f0.z; a0.w += f0.w;
        a1.x += f1.x; a1.y += f1.y; a1.z += f1.z; a1.w += f1.w;
    }
    if (j < len) {
        int s0 = __ldg(&g_csrc[start + j]);
        float4 f0 = __ldg(&g_x4[s0 * (D_FEAT / 4) + c]);
        a0.x += f0.x; a0.y += f0.y; a0.z += f0.z; a0.w += f0.w;
    }

    float nrm = __ldg(&g_norm[t]);
    out4[t * (D_FEAT / 4) + c] = make_float4((a0.x + a1.x) * nrm,
                                             (a0.y + a1.y) * nrm,
                                             (a0.z + a1.z) * nrm,
                                             (a0.w + a1.w) * nrm);
}

extern "C" void kernel_launch(void* const* d_in, const int* in_sizes, int n_in,
                              void* d_out, int out_size)
{
    const float* features = (const float*)d_in[0];
    const int*   src      = (const int*)d_in[1];
    const int*   dst      = (const int*)d_in[2];
    float*       out      = (float*)d_out;

    int n_nodes = in_sizes[0] / D_FEAT;   // 100000
    int n_edges = in_sizes[1];            // 1600000

    const int TPB = 256;
    int total4 = n_nodes * (D_FEAT / 4);
    int n4 = n_edges / 4;
    int scan_blocks = (n_nodes + SCAN_BLK - 1) / SCAN_BLK;   // 196

    k_init<<<(n_nodes + TPB - 1) / TPB, TPB>>>(n_nodes);

    k_degrees<<<(n4 + TPB - 1) / TPB, TPB>>>((const int4*)src, (const int4*)dst,
                                             src, dst, n4, n_edges);

    k_prescale<<<(total4 + TPB - 1) / TPB, TPB>>>((const float4*)features, n_nodes);

    k_scanA<<<scan_blocks, SCAN_BLK>>>(n_nodes);
    k_scanB<<<1, SCAN_BLK>>>(scan_blocks);
    k_scanC<<<scan_blocks, SCAN_BLK>>>(n_nodes);

    k_bucket<<<(n4 + TPB - 1) / TPB, TPB>>>((const int4*)src, (const int4*)dst,
                                            src, dst, n4, n_edges);

    int warps = (n_nodes + 3) / 4;
    long long threads = (long long)warps * 32;
    int blocks = (int)((threads + TPB - 1) / TPB);
    k_gather<<<blocks, TPB>>>((float4*)out, n_nodes);
}